// round 4
// baseline (speedup 1.0000x reference)
#include <cuda_runtime.h>

// Problem constants (fixed by the reference)
#define B_SZ 4096
#define T_SZ 2048

typedef unsigned long long u64;

// ---- f32x2 packed-math helpers (sm_103a) ----
__device__ __forceinline__ u64 pack2(float lo, float hi) {
    u64 r; asm("mov.b64 %0,{%1,%2};" : "=l"(r) : "f"(lo), "f"(hi)); return r;
}
__device__ __forceinline__ u64 bcast2(float v) { return pack2(v, v); }
__device__ __forceinline__ void unpack2(u64 p, float& a, float& b) {
    asm("mov.b64 {%0,%1},%2;" : "=f"(a), "=f"(b) : "l"(p));
}
__device__ __forceinline__ u64 fma2(u64 a, u64 b, u64 c) {
    u64 d; asm("fma.rn.f32x2 %0,%1,%2,%3;" : "=l"(d) : "l"(a), "l"(b), "l"(c)); return d;
}

// Weights into tanh layers are pre-scaled by K = 2*log2(e), so the
// accumulator is already 2*log2e*z and tanh costs only EX2,FADD,RCP,FFMA.
#define KSCALE 2.885390081777927f

__device__ __forceinline__ float tanh_pre(float zs) {
    float t = exp2f(zs);               // MUFU.EX2
    float d = t + 1.0f;
    float r; asm("rcp.approx.f32 %0, %1;" : "=f"(r) : "f"(d));  // MUFU.RCP
    return fmaf(-2.0f, r, 1.0f);       // tanh(z) = 1 - 2/(e^{2z}+1)
}

// Layout: 8 lanes per row. Each thread carries TWO rows (set A = CTA row g,
// set B = row g+16) skewed by half a step so one set's fma-heavy stage
// overlaps the other's MUFU-heavy stage. 128-thread CTAs, 128 CTAs,
// 1 warp/SMSP on 128 SMs.
__global__ void __launch_bounds__(128, 1)
msc_seq_kernel(const float* __restrict__ delta_seq,  // [B, T, 3]
               const float* __restrict__ state_0,    // [B, 5]
               const float* __restrict__ W1,         // [8, 32]
               const float* __restrict__ b1,         // [32]
               const float* __restrict__ W2,         // [32, 32]
               const float* __restrict__ b2,         // [32]
               const float* __restrict__ W3,         // [32, 5]
               const float* __restrict__ b3,         // [5]
               float* __restrict__ out)              // [B, T, 5]
{
    // h exchange buffers: row stride 18 u64 = 144B -> the 4 groups per warp
    // land on distinct bank quads for the broadcast LDS.128s.
    __shared__ __align__(16) u64 h1buf[32][18];
    __shared__ __align__(16) u64 h2buf[32][18];
    // Smem half of W2 (columns c1,c1+1 per lane), i-packed, K-prescaled.
    // Per-lane stride 34 u64 = 272B (odd multiple of 16B) -> conflict-free.
    __shared__ __align__(16) u64 w2s[8][34];

    const int tid = threadIdx.x;
    const int l   = tid & 7;            // lane within row
    const int g   = tid >> 3;           // group 0..15
    const int c0  = 2 * l;              // reg-half columns c0, c0+1
    const int c1  = 16 + 2 * l;         // smem-half columns c1, c1+1

    // cooperative w2s fill: 128 threads <-> 128 (lane, j) pairs
    {
        const int li = tid >> 4;        // 0..7
        const int j  = tid & 15;        // 0..15
        const int cc = 16 + 2 * li;
        w2s[li][2 * j + 0] = pack2(KSCALE * W2[(2 * j) * 32 + cc],
                                   KSCALE * W2[(2 * j + 1) * 32 + cc]);
        w2s[li][2 * j + 1] = pack2(KSCALE * W2[(2 * j) * 32 + cc + 1],
                                   KSCALE * W2[(2 * j + 1) * 32 + cc + 1]);
    }

    // ---- register-resident weights (K-prescaled where feeding tanh) ----
    u64 w1p[8][2];
    #pragma unroll
    for (int i = 0; i < 8; ++i) {
        w1p[i][0] = pack2(KSCALE * W1[i * 32 + c0], KSCALE * W1[i * 32 + c0 + 1]);
        w1p[i][1] = pack2(KSCALE * W1[i * 32 + c1], KSCALE * W1[i * 32 + c1 + 1]);
    }
    const u64 b1pA = pack2(KSCALE * b1[c0], KSCALE * b1[c0 + 1]);
    const u64 b1pB = pack2(KSCALE * b1[c1], KSCALE * b1[c1 + 1]);

    u64 w2r0[16], w2r1[16];   // i-packed reg half: columns c0, c0+1
    #pragma unroll
    for (int j = 0; j < 16; ++j) {
        w2r0[j] = pack2(KSCALE * W2[(2 * j) * 32 + c0],
                        KSCALE * W2[(2 * j + 1) * 32 + c0]);
        w2r1[j] = pack2(KSCALE * W2[(2 * j) * 32 + c0 + 1],
                        KSCALE * W2[(2 * j + 1) * 32 + c0 + 1]);
    }
    const u64 b2i0 = pack2(KSCALE * b2[c0], 0.0f);
    const u64 b2i1 = pack2(KSCALE * b2[c0 + 1], 0.0f);
    const u64 b2i2 = pack2(KSCALE * b2[c1], 0.0f);
    const u64 b2i3 = pack2(KSCALE * b2[c1 + 1], 0.0f);

    // layer-3 (NOT scaled): my output element s, i-packed down W3 column s
    const int s = (l < 5) ? l : 0;
    u64 w3c[16];
    #pragma unroll
    for (int j = 0; j < 16; ++j)
        w3c[j] = pack2(W3[(2 * j) * 5 + s], W3[(2 * j + 1) * 5 + s]);
    const u64 b3i = pack2(b3[s], 0.0f);

    __syncthreads();  // w2s ready

    const int rowA = blockIdx.x * 32 + g;
    const int rowB = rowA + 16;
    const float* dA = delta_seq + (size_t)rowA * T_SZ * 3;
    const float* dB = delta_seq + (size_t)rowB * T_SZ * 3;
    float* oA = out + (size_t)rowA * T_SZ * 5;
    float* oB = out + (size_t)rowB * T_SZ * 5;

    float stA = state_0[rowA * 5 + s];
    float stB = state_0[rowB * 5 + s];
    float dnA0 = __ldg(dA + 0), dnA1 = __ldg(dA + 1), dnA2 = __ldg(dA + 2);
    float dnB0 = __ldg(dB + 0), dnB1 = __ldg(dB + 1), dnB2 = __ldg(dB + 2);

    // ---- stage S1: state bcast, layer1, tanh, publish h1; prefetch delta ----
    auto S1 = [&](int rr, float& st, float& n0, float& n1, float& n2,
                  const float* dbase, int t) {
        const float s0 = __shfl_sync(0xffffffffu, st, 0, 8);
        const float s1 = __shfl_sync(0xffffffffu, st, 1, 8);
        const float s2 = __shfl_sync(0xffffffffu, st, 2, 8);
        const float s3 = __shfl_sync(0xffffffffu, st, 3, 8);
        const float s4 = __shfl_sync(0xffffffffu, st, 4, 8);
        const float d0 = n0, d1 = n1, d2 = n2;
        const int tn = (t + 1 < T_SZ) ? (t + 1) : t;
        n0 = __ldg(dbase + tn * 3 + 0);
        n1 = __ldg(dbase + tn * 3 + 1);
        n2 = __ldg(dbase + tn * 3 + 2);

        u64 aA = b1pA, aB = b1pB, x;
        x = bcast2(s0); aA = fma2(x, w1p[0][0], aA); aB = fma2(x, w1p[0][1], aB);
        x = bcast2(s1); aA = fma2(x, w1p[1][0], aA); aB = fma2(x, w1p[1][1], aB);
        x = bcast2(s2); aA = fma2(x, w1p[2][0], aA); aB = fma2(x, w1p[2][1], aB);
        x = bcast2(s3); aA = fma2(x, w1p[3][0], aA); aB = fma2(x, w1p[3][1], aB);
        x = bcast2(s4); aA = fma2(x, w1p[4][0], aA); aB = fma2(x, w1p[4][1], aB);
        x = bcast2(d0); aA = fma2(x, w1p[5][0], aA); aB = fma2(x, w1p[5][1], aB);
        x = bcast2(d1); aA = fma2(x, w1p[6][0], aA); aB = fma2(x, w1p[6][1], aB);
        x = bcast2(d2); aA = fma2(x, w1p[7][0], aA); aB = fma2(x, w1p[7][1], aB);

        float h0, h1v, h2v, h3;
        unpack2(aA, h0, h1v);
        unpack2(aB, h2v, h3);
        h0 = tanh_pre(h0); h1v = tanh_pre(h1v);
        h2v = tanh_pre(h2v); h3 = tanh_pre(h3);
        h1buf[rr][l]     = pack2(h0, h1v);
        h1buf[rr][8 + l] = pack2(h2v, h3);
    };

    // ---- stage S2: layer2 (half weights reg, half smem), tanh, publish h2 ----
    auto S2 = [&](int rr) {
        u64 a0 = b2i0, a1 = b2i1, a2 = b2i2, a3 = b2i3;
        #pragma unroll
        for (int k = 0; k < 8; ++k) {
            ulonglong2 hp = *(const ulonglong2*)&h1buf[rr][2 * k];
            ulonglong2 wv0 = *(const ulonglong2*)&w2s[l][4 * k];
            ulonglong2 wv1 = *(const ulonglong2*)&w2s[l][4 * k + 2];
            a0 = fma2(hp.x, w2r0[2 * k], a0);
            a1 = fma2(hp.x, w2r1[2 * k], a1);
            a2 = fma2(hp.x, wv0.x, a2);
            a3 = fma2(hp.x, wv0.y, a3);
            a0 = fma2(hp.y, w2r0[2 * k + 1], a0);
            a1 = fma2(hp.y, w2r1[2 * k + 1], a1);
            a2 = fma2(hp.y, wv1.x, a2);
            a3 = fma2(hp.y, wv1.y, a3);
        }
        float lo, hi, g0, g1, g2, g3;
        unpack2(a0, lo, hi); g0 = tanh_pre(lo + hi);
        unpack2(a1, lo, hi); g1 = tanh_pre(lo + hi);
        unpack2(a2, lo, hi); g2 = tanh_pre(lo + hi);
        unpack2(a3, lo, hi); g3 = tanh_pre(lo + hi);
        h2buf[rr][l]     = pack2(g0, g1);
        h2buf[rr][8 + l] = pack2(g2, g3);
    };

    // ---- stage S3: layer3 dot (output-owned), residual update, store ----
    auto S3 = [&](int rr, float& st, float* obase, int t) {
        u64 pa = b3i, pb = pack2(0.0f, 0.0f);
        #pragma unroll
        for (int k = 0; k < 8; ++k) {
            ulonglong2 hp = *(const ulonglong2*)&h2buf[rr][2 * k];
            pa = fma2(hp.x, w3c[2 * k], pa);
            pb = fma2(hp.y, w3c[2 * k + 1], pb);
        }
        float pl0, ph0, pl1, ph1;
        unpack2(pa, pl0, ph0);
        unpack2(pb, pl1, ph1);
        st += (pl0 + ph0) + (pl1 + ph1);
        if (l < 5) obase[t * 5 + l] = st;
    };

    const int rA = g, rB = g + 16;

    // ---- skewed pipeline: B runs half a step behind A ----
    S1(rA, stA, dnA0, dnA1, dnA2, dA, 0);
    for (int t = 0; t < T_SZ; ++t) {
        __syncwarp();
        // phase 1: A fma-heavy (L2), B MUFU-heavy (L3-prev + L1)
        S2(rA);
        if (t) S3(rB, stB, oB, t - 1);
        S1(rB, stB, dnB0, dnB1, dnB2, dB, t);
        __syncwarp();
        // phase 2: A L3 + next L1 (MUFU-heavy), B fma-heavy (L2)
        S3(rA, stA, oA, t);
        if (t + 1 < T_SZ) S1(rA, stA, dnA0, dnA1, dnA2, dA, t + 1);
        S2(rB);
    }
    __syncwarp();
    S3(rB, stB, oB, T_SZ - 1);
}

extern "C" void kernel_launch(void* const* d_in, const int* in_sizes, int n_in,
                              void* d_out, int out_size) {
    (void)in_sizes; (void)n_in; (void)out_size;
    const float* delta_seq = (const float*)d_in[0];
    const float* state_0   = (const float*)d_in[1];
    const float* W1        = (const float*)d_in[2];
    const float* b1        = (const float*)d_in[3];
    const float* W2        = (const float*)d_in[4];
    const float* b2        = (const float*)d_in[5];
    const float* W3        = (const float*)d_in[6];
    const float* b3        = (const float*)d_in[7];
    float* out             = (float*)d_out;

    msc_seq_kernel<<<B_SZ / 32, 128>>>(delta_seq, state_0, W1, b1, W2, b2, W3, b3, out);
}

// round 5
// speedup vs baseline: 1.4567x; 1.4567x over previous
#include <cuda_runtime.h>

// Problem constants (fixed by the reference)
#define B_SZ 4096
#define T_SZ 2048

typedef unsigned long long u64;

// ---- f32x2 packed-math helpers (sm_103a) ----
__device__ __forceinline__ u64 pack2(float lo, float hi) {
    u64 r; asm("mov.b64 %0,{%1,%2};" : "=l"(r) : "f"(lo), "f"(hi)); return r;
}
__device__ __forceinline__ u64 bcast2(float v) { return pack2(v, v); }
__device__ __forceinline__ void unpack2(u64 p, float& a, float& b) {
    asm("mov.b64 {%0,%1},%2;" : "=f"(a), "=f"(b) : "l"(p));
}
__device__ __forceinline__ u64 fma2(u64 a, u64 b, u64 c) {
    u64 d; asm("fma.rn.f32x2 %0,%1,%2,%3;" : "=l"(d) : "l"(a), "l"(b), "l"(c)); return d;
}
__device__ __forceinline__ u64 add2(u64 a, u64 b) {
    u64 d; asm("add.rn.f32x2 %0,%1,%2;" : "=l"(d) : "l"(a), "l"(b)); return d;
}

// Weights feeding tanh are pre-scaled by K = 2*log2(e): acc = 2*log2e*z,
// so tanh(z) = 1 - 2/(2^acc + 1) costs EX2, FADD, RCP, FMA only.
#define KSCALE 2.885390081777927f

__device__ __forceinline__ float tanh_pre(float zs) {
    float t; asm("ex2.approx.f32 %0,%1;" : "=f"(t) : "f"(zs));
    float d = t + 1.0f;
    float r; asm("rcp.approx.f32 %0,%1;" : "=f"(r) : "f"(d));
    return fmaf(-2.0f, r, 1.0f);
}

// Layout (same as R3): 8 lanes/row, 4 rows/warp, 32 rows per 256-thread CTA,
// 128 CTAs. Lane l owns hidden cols {2l,2l+1,16+2l,16+2l+1}. h exchanged via
// padded smem. NEW: warps 4-7 run one pipeline stage ahead of warps 0-3 so
// the two warps sharing each SMSP (wid, wid+4) have decorrelated pipe phases
// (MUFU burst of one overlaps FMA burst of the other).
__global__ void __launch_bounds__(256, 1)
msc_seq_kernel(const float* __restrict__ delta_seq,  // [B, T, 3]
               const float* __restrict__ state_0,    // [B, 5]
               const float* __restrict__ W1,         // [8, 32]
               const float* __restrict__ b1,         // [32]
               const float* __restrict__ W2,         // [32, 32]
               const float* __restrict__ b2,         // [32]
               const float* __restrict__ W3,         // [32, 5]
               const float* __restrict__ b3,         // [5]
               float* __restrict__ out)              // [B, T, 5]
{
    // Row stride 18 u64 = 144B: 4 warp-rows land on distinct bank quads.
    __shared__ __align__(16) u64 h1buf[32][18];
    __shared__ __align__(16) u64 h2buf[32][18];

    const int tid = threadIdx.x;
    const int l   = tid & 7;                 // lane within row
    const int r   = tid >> 3;                // row within CTA (0..31)
    const int row = blockIdx.x * 32 + r;
    const int c0  = 2 * l;
    const int c1  = 16 + 2 * l;

    // ---- layer-1 weights, column-packed, K-prescaled ----
    u64 w1p[8][2];
    #pragma unroll
    for (int i = 0; i < 8; ++i) {
        w1p[i][0] = pack2(KSCALE * W1[i * 32 + c0], KSCALE * W1[i * 32 + c0 + 1]);
        w1p[i][1] = pack2(KSCALE * W1[i * 32 + c1], KSCALE * W1[i * 32 + c1 + 1]);
    }
    const u64 b1pA = pack2(KSCALE * b1[c0], KSCALE * b1[c0 + 1]);
    const u64 b1pB = pack2(KSCALE * b1[c1], KSCALE * b1[c1 + 1]);

    // ---- layer-2 weights, i-packed per owned column, K-prescaled ----
    u64 w2c[4][16];
    {
        const int cols[4] = { c0, c0 + 1, c1, c1 + 1 };
        #pragma unroll
        for (int c = 0; c < 4; ++c)
            #pragma unroll
            for (int j = 0; j < 16; ++j)
                w2c[c][j] = pack2(KSCALE * W2[(2 * j) * 32 + cols[c]],
                                  KSCALE * W2[(2 * j + 1) * 32 + cols[c]]);
    }
    u64 b2i[4];
    {
        const int cols[4] = { c0, c0 + 1, c1, c1 + 1 };
        #pragma unroll
        for (int c = 0; c < 4; ++c) b2i[c] = pack2(KSCALE * b2[cols[c]], 0.0f);
    }

    // ---- layer-3 weights (NOT scaled): output element s, i-packed ----
    const int s = (l < 5) ? l : 0;
    u64 w3c[16];
    #pragma unroll
    for (int j = 0; j < 16; ++j)
        w3c[j] = pack2(W3[(2 * j) * 5 + s], W3[(2 * j + 1) * 5 + s]);
    const u64 b3i = pack2(b3[s], 0.0f);

    float st = state_0[row * 5 + s];

    const float* dptr = delta_seq + (size_t)row * T_SZ * 3;
    float* optr = out + (size_t)row * T_SZ * 5;
    float dn0 = __ldg(dptr + 0), dn1 = __ldg(dptr + 1), dn2 = __ldg(dptr + 2);

    // ---- S1: state bcast, layer1 (split 4-deep chains), tanh, publish h1 ----
    auto S1 = [&](int t) {
        const float s0 = __shfl_sync(0xffffffffu, st, 0, 8);
        const float s1 = __shfl_sync(0xffffffffu, st, 1, 8);
        const float s2 = __shfl_sync(0xffffffffu, st, 2, 8);
        const float s3 = __shfl_sync(0xffffffffu, st, 3, 8);
        const float s4 = __shfl_sync(0xffffffffu, st, 4, 8);
        const float d0 = dn0, d1 = dn1, d2 = dn2;
        const int tn = (t + 1 < T_SZ) ? (t + 1) : t;
        dn0 = __ldg(dptr + tn * 3 + 0);
        dn1 = __ldg(dptr + tn * 3 + 1);
        dn2 = __ldg(dptr + tn * 3 + 2);

        u64 aA = b1pA, aB = b1pB;                       // chain 1 (i=0..3)
        u64 cA = bcast2(0.0f), cB = cA;                 // chain 2 (i=4..7)
        u64 x;
        x = bcast2(s0); aA = fma2(x, w1p[0][0], aA); aB = fma2(x, w1p[0][1], aB);
        x = bcast2(s1); aA = fma2(x, w1p[1][0], aA); aB = fma2(x, w1p[1][1], aB);
        x = bcast2(s2); aA = fma2(x, w1p[2][0], aA); aB = fma2(x, w1p[2][1], aB);
        x = bcast2(s3); aA = fma2(x, w1p[3][0], aA); aB = fma2(x, w1p[3][1], aB);
        x = bcast2(s4); cA = fma2(x, w1p[4][0], cA); cB = fma2(x, w1p[4][1], cB);
        x = bcast2(d0); cA = fma2(x, w1p[5][0], cA); cB = fma2(x, w1p[5][1], cB);
        x = bcast2(d1); cA = fma2(x, w1p[6][0], cA); cB = fma2(x, w1p[6][1], cB);
        x = bcast2(d2); cA = fma2(x, w1p[7][0], cA); cB = fma2(x, w1p[7][1], cB);
        aA = add2(aA, cA);
        aB = add2(aB, cB);

        float h0, h1v, h2v, h3;
        unpack2(aA, h0, h1v);
        unpack2(aB, h2v, h3);
        h0 = tanh_pre(h0); h1v = tanh_pre(h1v);
        h2v = tanh_pre(h2v); h3 = tanh_pre(h3);
        h1buf[r][l]     = pack2(h0, h1v);
        h1buf[r][8 + l] = pack2(h2v, h3);
    };

    // ---- S2: layer2 (reg weights, i-packed), tanh, publish h2 ----
    auto S2 = [&]() {
        u64 a0 = b2i[0], a1 = b2i[1], a2 = b2i[2], a3 = b2i[3];
        #pragma unroll
        for (int k = 0; k < 8; ++k) {
            ulonglong2 hp = *(const ulonglong2*)&h1buf[r][2 * k];
            a0 = fma2(hp.x, w2c[0][2 * k], a0);
            a1 = fma2(hp.x, w2c[1][2 * k], a1);
            a2 = fma2(hp.x, w2c[2][2 * k], a2);
            a3 = fma2(hp.x, w2c[3][2 * k], a3);
            a0 = fma2(hp.y, w2c[0][2 * k + 1], a0);
            a1 = fma2(hp.y, w2c[1][2 * k + 1], a1);
            a2 = fma2(hp.y, w2c[2][2 * k + 1], a2);
            a3 = fma2(hp.y, w2c[3][2 * k + 1], a3);
        }
        float lo, hi, g0, g1, g2, g3;
        unpack2(a0, lo, hi); g0 = tanh_pre(lo + hi);
        unpack2(a1, lo, hi); g1 = tanh_pre(lo + hi);
        unpack2(a2, lo, hi); g2 = tanh_pre(lo + hi);
        unpack2(a3, lo, hi); g3 = tanh_pre(lo + hi);
        h2buf[r][l]     = pack2(g0, g1);
        h2buf[r][8 + l] = pack2(g2, g3);
    };

    // ---- S3: layer3 dot (output-owned), residual update, store ----
    auto S3 = [&](int t) {
        u64 pa = b3i, pb = bcast2(0.0f);
        #pragma unroll
        for (int k = 0; k < 8; ++k) {
            ulonglong2 hp = *(const ulonglong2*)&h2buf[r][2 * k];
            pa = fma2(hp.x, w3c[2 * k], pa);
            pb = fma2(hp.y, w3c[2 * k + 1], pb);
        }
        float pl0, ph0, pl1, ph1;
        unpack2(pa, pl0, ph0);
        unpack2(pb, pl1, ph1);
        st += (pl0 + ph0) + (pl1 + ph1);
        if (l < 5) optr[t * 5 + l] = st;
    };

    // ---- phase-skewed execution: warps 0-3 vs warps 4-7 ----
    // SMSP sp hosts wid sp and sp+4 (wid%4): exactly one of each parity.
    // No inter-warp dependency exists, so the skew persists for all 2048 steps.
    if (tid < 128) {
        for (int t = 0; t < T_SZ; ++t) {
            S1(t);
            __syncwarp();
            S2();
            __syncwarp();
            S3(t);
        }
    } else {
        S1(0);
        __syncwarp();
        S2();
        __syncwarp();
        for (int t = 0; t < T_SZ - 1; ++t) {
            S3(t);
            S1(t + 1);
            __syncwarp();
            S2();
            __syncwarp();
        }
        S3(T_SZ - 1);
    }
}

extern "C" void kernel_launch(void* const* d_in, const int* in_sizes, int n_in,
                              void* d_out, int out_size) {
    (void)in_sizes; (void)n_in; (void)out_size;
    const float* delta_seq = (const float*)d_in[0];
    const float* state_0   = (const float*)d_in[1];
    const float* W1        = (const float*)d_in[2];
    const float* b1        = (const float*)d_in[3];
    const float* W2        = (const float*)d_in[4];
    const float* b2        = (const float*)d_in[5];
    const float* W3        = (const float*)d_in[6];
    const float* b3        = (const float*)d_in[7];
    float* out             = (float*)d_out;

    msc_seq_kernel<<<B_SZ / 32, 256>>>(delta_seq, state_0, W1, b1, W2, b2, W3, b3, out);
}